// round 11
// baseline (speedup 1.0000x reference)
#include <cuda_runtime.h>
#include <cuda_bf16.h>

#define C    256
#define C4   64          // C / 4
#define H    200
#define W    200
#define HP   201
#define WP   201
#define NBOX 1024
#define OH   7
#define OW   7
#define SEG  20          // y-scan segments
#define LSEG 10          // 200 / 20

// Integral image [r][k][c] (channel-innermost). After yscan_kernel rows hold
// within-segment partial y-scans of the full x-scan.
__device__ float g_ii[HP * WP * C];          // 41.4 MB
// Per-y-segment totals -> exclusive prefix (y fixup), [seg][k][c], k=0..200
__device__ float g_ysum[SEG * WP * C];       // 4.1 MB

// ---------------------------------------------------------------------------
// Kernel A: fused transpose + FULL x-scan (no segmentation).
// One warp per (channel, y) row. Coalesced 128B chunk loads from fm[c][y][x],
// 5-step shuffle inclusive scan + running carry, stage into conflict-free
// smem (stride 33), then write channel-innermost g_ii rows as 128B lines.
// grid = (H, C/32), block = 1024 (32 warps = 32 channels, one y).
// ---------------------------------------------------------------------------
__global__ void __launch_bounds__(1024) xscanT_kernel(const float* __restrict__ fm) {
    __shared__ float s[W * 33];               // 26.4 KB, [x][c_local] stride 33
    const int y  = blockIdx.x;
    const int c0 = blockIdx.y * 32;
    const int w  = threadIdx.x >> 5;          // warp = local channel
    const int l  = threadIdx.x & 31;

    const float* row = fm + ((c0 + w) * H + y) * W;
    float carry = 0.f;
#pragma unroll
    for (int ch = 0; ch < 7; ch++) {          // 7*32 = 224 >= 200
        int x = ch * 32 + l;
        float v = (x < W) ? row[x] : 0.f;
#pragma unroll
        for (int d = 1; d < 32; d <<= 1) {
            float t = __shfl_up_sync(0xffffffffu, v, d);
            if (l >= d) v += t;
        }
        if (x < W) s[x * 33 + w] = carry + v;
        carry += __shfl_sync(0xffffffffu, v, 31);
    }
    __syncthreads();
    // Write phase: warp w writes x-rows w, w+32, ... ; 128B coalesced lines.
    for (int x = w; x < W; x += 32)
        g_ii[((y + 1) * WP + (x + 1)) * C + c0 + l] = s[x * 33 + l];
}

// ---------------------------------------------------------------------------
// Kernel B: segmented y-scan over the x-scanned rows, float4 over channels.
// Thread per (y-seg, k-1, c4); chain length LSEG=10. 256,000 threads.
// Emits per-segment totals into g_ysum[seg][k][c].
// ---------------------------------------------------------------------------
__global__ void __launch_bounds__(256) yscan_kernel() {
    int t  = blockIdx.x * blockDim.x + threadIdx.x;
    int c4 = t & (C4 - 1);
    int x  = (t >> 6) % W;                    // k = x + 1
    int sy = t / (C4 * W);
    float4* ii = (float4*)g_ii;
    float4 run = {0.f, 0.f, 0.f, 0.f};
    int y0 = sy * LSEG;
#pragma unroll 5
    for (int yy = 0; yy < LSEG; yy++) {
        int r   = y0 + yy + 1;
        int off = (r * WP + (x + 1)) * C4 + c4;
        float4 v = ii[off];
        run.x += v.x; run.y += v.y; run.z += v.z; run.w += v.w;
        ii[off] = run;
    }
    ((float4*)g_ysum)[(sy * WP + (x + 1)) * C4 + c4] = run;
}

// ---------------------------------------------------------------------------
// Kernel C: warp-shuffle exclusive prefix over SEG y-segment totals
// (one warp per (k, c4); lane = segment) + zero g_ii borders.
// k==0 lanes load 0 -> writes zeros into the k==0 column of g_ysum.
// ---------------------------------------------------------------------------
#define NPFXW (WP * C4)                       // 12,864 warp tasks
__global__ void __launch_bounds__(256) ysum_prefix_border_kernel() {
    int tid = blockIdx.x * blockDim.x + threadIdx.x;
    if (tid < NPFXW * 32) {
        int wid = tid >> 5;
        int lane = tid & 31;
        int k  = wid / C4;
        int c4 = wid % C4;
        float4* p = (float4*)g_ysum;
        float4 v = {0.f, 0.f, 0.f, 0.f};
        if (lane < SEG && k > 0)
            v = p[(lane * WP + k) * C4 + c4];
        float4 incl = v;
#pragma unroll
        for (int d = 1; d < 32; d <<= 1) {
            float tx = __shfl_up_sync(0xffffffffu, incl.x, d);
            float ty = __shfl_up_sync(0xffffffffu, incl.y, d);
            float tz = __shfl_up_sync(0xffffffffu, incl.z, d);
            float tw = __shfl_up_sync(0xffffffffu, incl.w, d);
            if (lane >= d) { incl.x += tx; incl.y += ty; incl.z += tz; incl.w += tw; }
        }
        if (lane < SEG) {
            float4 excl = {incl.x - v.x, incl.y - v.y, incl.z - v.z, incl.w - v.w};
            p[(lane * WP + k) * C4 + c4] = excl;
        }
    } else {
        int t2 = tid - NPFXW * 32;
        const float4 z = {0.f, 0.f, 0.f, 0.f};
        if (t2 < WP * C4) {
            ((float4*)g_ii)[t2] = z;                      // row r==0
        } else if (t2 < WP * C4 + H * C4) {
            int kk = t2 - WP * C4;
            int r  = kk / C4 + 1;
            int c4 = kk & (C4 - 1);
            ((float4*)g_ii)[(r * WP) * C4 + c4] = z;      // col k==0
        }
    }
}

// ---------------------------------------------------------------------------
// Kernel D: ROI pooling output. One block per box, one thread per channel.
// Full corner value = ii_partial(r,k) + ysumPfx(segOf(r), k); 8 coalesced
// gathers per bin (ysumPfx lines are L1-resident). Output staged in smem,
// flushed with coalesced float4.
// ---------------------------------------------------------------------------
__global__ void __launch_bounds__(C) roi_kernel(const float* __restrict__ boxes,
                                                float* __restrict__ out)
{
    extern __shared__ float s_out[];                 // C*49 floats = 50176 B
    __shared__ int   s_rs[OH], s_re[OH], s_cs[OW], s_ce[OW];
    __shared__ int   s_rsSeg[OH], s_reSeg[OH];
    __shared__ float s_inv[OH * OW];

    const int n = blockIdx.x;
    const int c = threadIdx.x;

    if (c < OH) {
        const float sc = 0.25f;                      // 200/800, exact in fp32
        int bx1 = (int)floorf(boxes[n * 4 + 0] * sc);
        int by1 = (int)floorf(boxes[n * 4 + 1] * sc);
        int bx2 = (int)floorf(boxes[n * 4 + 2] * sc);
        int by2 = (int)floorf(boxes[n * 4 + 3] * sc);
        int x1 = min(max(bx1, 0), W - 1);
        int y1 = min(max(by1, 0), H - 1);
        int x2 = min(max(bx2 + 1, x1 + 1), W);
        int y2 = min(max(by2 + 1, y1 + 1), H);
        int rh = y2 - y1, rw = x2 - x1;
        int i = c;
        int rsv = y1 + (i * rh) / OH;
        int rev = y1 + ((i + 1) * rh + OH - 1) / OH;
        s_rs[i] = rsv;
        s_re[i] = rev;
        s_rsSeg[i] = max(rsv - 1, 0) / LSEG;         // rs==0 -> seg0 (prefix 0)
        s_reSeg[i] = (rev - 1) / LSEG;               // re >= 1 always
        s_cs[i] = x1 + (i * rw) / OW;
        s_ce[i] = x1 + ((i + 1) * rw + OW - 1) / OW;
    }
    __syncthreads();
    if (c < OH * OW) {
        int i = c / OW, j = c % OW;
        s_inv[c] = 1.0f / (float)((s_re[i] - s_rs[i]) * (s_ce[j] - s_cs[j]));
    }
    __syncthreads();

    const float* ii = g_ii + c;
    const float* yp = g_ysum + c;

#pragma unroll
    for (int i = 0; i < OH; i++) {
        int rA = s_rs[i],    rB = s_re[i];
        int sA = s_rsSeg[i], sB = s_reSeg[i];
#pragma unroll
        for (int j = 0; j < OW; j++) {
            int kA = s_cs[j], kB = s_ce[j];
            float v = ii[(rB * WP + kB) * C] + yp[(sB * WP + kB) * C]
                    - ii[(rA * WP + kB) * C] - yp[(sA * WP + kB) * C]
                    - ii[(rB * WP + kA) * C] - yp[(sB * WP + kA) * C]
                    + ii[(rA * WP + kA) * C] + yp[(sA * WP + kA) * C];
            s_out[c * (OH * OW) + i * OW + j] = v * s_inv[i * OW + j];
        }
    }
    __syncthreads();

    // Coalesced float4 flush: 12544 floats = 3136 float4, base 16B-aligned.
    float4*       dst = (float4*)(out + (size_t)n * C * (OH * OW));
    const float4* src = (const float4*)s_out;
    for (int idx = c; idx < (C * OH * OW) / 4; idx += C)
        dst[idx] = src[idx];
}

// ---------------------------------------------------------------------------
extern "C" void kernel_launch(void* const* d_in, const int* in_sizes, int n_in,
                              void* d_out, int out_size)
{
    const float* fm    = (const float*)d_in[0];
    const float* boxes = (const float*)d_in[1];
    if (n_in >= 2 && in_sizes[0] < in_sizes[1]) {
        fm    = (const float*)d_in[1];
        boxes = (const float*)d_in[0];
    }
    float* out = (float*)d_out;

    // roi_kernel needs 50176 B dynamic smem (> 48 KB default)
    cudaFuncSetAttribute(roi_kernel, cudaFuncAttributeMaxDynamicSharedMemorySize,
                         C * OH * OW * (int)sizeof(float));

    // 1) fused transpose + full x-scan (warp shuffle)
    {
        dim3 grid(H, C / 32);
        xscanT_kernel<<<grid, 1024>>>(fm);
    }
    // 2) segmented y-scan (float4), emits segment totals
    yscan_kernel<<<(SEG * W * C4) / 256, 256>>>();
    // 3) warp-shuffle exclusive prefix over segment totals + border zeroing
    {
        int total = NPFXW * 32 + WP * C4 + H * C4;
        ysum_prefix_border_kernel<<<(total + 255) / 256, 256>>>();
    }
    // 4) ROI pooling output (y-fixup fused into gather)
    roi_kernel<<<NBOX, C, C * OH * OW * (int)sizeof(float)>>>(boxes, out);
}

// round 12
// speedup vs baseline: 1.3875x; 1.3875x over previous
#include <cuda_runtime.h>
#include <cuda_bf16.h>

#define C    256
#define C4   64          // C / 4
#define H    200
#define W    200
#define HP   201
#define WP   201
#define NBOX 1024
#define OH   7
#define OW   7
#define SEG  20          // segments for BOTH y-scan and x-scan
#define LSEG 10          // 200 / 20
#define YCH  5           // y-rows per smem chunk in yscan
#define SOPITCH 260      // smem staging pitch (floats per bin row, 16B-aligned)

// Integral image [r][col][c] (channel-innermost); partial-x-scan after xscan_kernel
__device__ float g_ii[HP * WP * C];          // 41.4 MB
// Per-y-segment column totals -> exclusive prefix (y fixup), [seg][x][c]
__device__ float g_colsum[SEG * W * C];      // 4.1 MB
// Per-x-segment row totals -> exclusive prefix (x fixup), [seg][r][c]
__device__ float g_rowsum[SEG * HP * C];     // 4.1 MB

// ---------------------------------------------------------------------------
// Kernel 1: fused transpose + segmented y-scan (R10 champion, unchanged).
// ---------------------------------------------------------------------------
__global__ void __launch_bounds__(256) yscan_kernel(const float* __restrict__ fm) {
    __shared__ float tile[YCH][32][33];   // [y][c_local][x_local]
    const int x0 = blockIdx.x * 32;
    const int c0 = blockIdx.y * 32;
    const int y0 = blockIdx.z * LSEG;
    const int tx = threadIdx.x;           // 0..31
    const int ty = threadIdx.y;           // 0..7
    const int cS = c0 + tx;               // owned channel (store side)
    const bool xinL = (x0 + tx) < W;

    float run[4] = {0.f, 0.f, 0.f, 0.f};

#pragma unroll
    for (int ch = 0; ch < LSEG / YCH; ch++) {
        int yb = y0 + ch * YCH;
#pragma unroll
        for (int yy = 0; yy < YCH; yy++) {
#pragma unroll
            for (int k = 0; k < 4; k++) {
                int cl = ty + 8 * k;
                tile[yy][cl][tx] =
                    xinL ? fm[((c0 + cl) * H + (yb + yy)) * W + (x0 + tx)] : 0.f;
            }
        }
        __syncthreads();
#pragma unroll
        for (int yy = 0; yy < YCH; yy++) {
            int y = yb + yy;
#pragma unroll
            for (int k = 0; k < 4; k++) {
                int xl = ty + 8 * k;
                run[k] += tile[yy][tx][xl];
                int x = x0 + xl;
                if (x < W)
                    g_ii[((y + 1) * WP + (x + 1)) * C + cS] = run[k];
            }
        }
        __syncthreads();
    }
#pragma unroll
    for (int k = 0; k < 4; k++) {
        int x = x0 + ty + 8 * k;
        if (x < W)
            g_colsum[(blockIdx.z * W + x) * C + cS] = run[k];
    }
}

// ---------------------------------------------------------------------------
// Kernel 2: warp-shuffle exclusive prefix over SEG y-segment totals.
// One warp per (x, c4), lane = segment. 409,600 threads.
// ---------------------------------------------------------------------------
__global__ void __launch_bounds__(256) colprefix_kernel() {
    int tid  = blockIdx.x * blockDim.x + threadIdx.x;
    int wid  = tid >> 5;
    int lane = tid & 31;
    if (wid >= W * C4) return;
    int x  = wid / C4;
    int c4 = wid % C4;
    float4* p = (float4*)g_colsum;
    float4 v = {0.f, 0.f, 0.f, 0.f};
    if (lane < SEG) v = p[(lane * W + x) * C4 + c4];
    float4 s = v;
#pragma unroll
    for (int d = 1; d < 32; d <<= 1) {
        float ax = __shfl_up_sync(0xffffffffu, s.x, d);
        float ay = __shfl_up_sync(0xffffffffu, s.y, d);
        float az = __shfl_up_sync(0xffffffffu, s.z, d);
        float aw = __shfl_up_sync(0xffffffffu, s.w, d);
        if (lane >= d) { s.x += ax; s.y += ay; s.z += az; s.w += aw; }
    }
    if (lane < SEG) {
        float4 e = {s.x - v.x, s.y - v.y, s.z - v.z, s.w - v.w};
        p[(lane * W + x) * C4 + c4] = e;
    }
}

// ---------------------------------------------------------------------------
// Kernel 3: segmented x-scan + fused y-fixup, float4 (R10 champion, unchanged).
// ---------------------------------------------------------------------------
__global__ void __launch_bounds__(256) xscan_kernel() {
    int t  = blockIdx.x * blockDim.x + threadIdx.x;
    int c4 = t & (C4 - 1);
    int y  = (t >> 6) % H;
    int sx = t / (C4 * H);
    int sy = y / LSEG;
    int r  = y + 1;
    float4* ii = (float4*)g_ii;
    const float4* cp = (const float4*)g_colsum + (sy * W) * C4 + c4;
    float4 run = {0.f, 0.f, 0.f, 0.f};
    int x0 = sx * LSEG;
#pragma unroll 5
    for (int xx = 0; xx < LSEG; xx++) {
        int x   = x0 + xx;
        int off = (r * WP + (x + 1)) * C4 + c4;
        float4 v = ii[off];
        float4 a = cp[x * C4];
        run.x += v.x + a.x;
        run.y += v.y + a.y;
        run.z += v.z + a.z;
        run.w += v.w + a.w;
        ii[off] = run;
    }
    ((float4*)g_rowsum)[(sx * HP + r) * C4 + c4] = run;
}

// ---------------------------------------------------------------------------
// Kernel 4: warp-shuffle exclusive prefix over SEG x-segment totals
// (one warp per (r, c4), lane = segment; r==0 forced to 0) + border zeroing.
// ---------------------------------------------------------------------------
#define NPFXW (HP * C4)                   // 12,864 warp tasks
__global__ void __launch_bounds__(256) rowprefix_border_kernel() {
    int tid = blockIdx.x * blockDim.x + threadIdx.x;
    if (tid < NPFXW * 32) {
        int wid  = tid >> 5;
        int lane = tid & 31;
        int r  = wid / C4;
        int c4 = wid % C4;
        float4* p = (float4*)g_rowsum;
        float4 v = {0.f, 0.f, 0.f, 0.f};
        if (lane < SEG && r > 0) v = p[(lane * HP + r) * C4 + c4];
        float4 s = v;
#pragma unroll
        for (int d = 1; d < 32; d <<= 1) {
            float ax = __shfl_up_sync(0xffffffffu, s.x, d);
            float ay = __shfl_up_sync(0xffffffffu, s.y, d);
            float az = __shfl_up_sync(0xffffffffu, s.z, d);
            float aw = __shfl_up_sync(0xffffffffu, s.w, d);
            if (lane >= d) { s.x += ax; s.y += ay; s.z += az; s.w += aw; }
        }
        if (lane < SEG) {
            float4 e = {s.x - v.x, s.y - v.y, s.z - v.z, s.w - v.w};
            p[(lane * HP + r) * C4 + c4] = e;
        }
    } else {
        int t2 = tid - NPFXW * 32;
        const float4 z = {0.f, 0.f, 0.f, 0.f};
        if (t2 < WP * C4) {
            ((float4*)g_ii)[t2] = z;                      // row r==0
        } else if (t2 < WP * C4 + H * C4) {
            int kk = t2 - WP * C4;
            int r  = kk / C4 + 1;
            int c4 = kk & (C4 - 1);
            ((float4*)g_ii)[(r * WP) * C4 + c4] = z;      // col k==0
        }
    }
}

// ---------------------------------------------------------------------------
// Kernel 5: ROI pooling output, float4 over channels.
// Thread t = bg*64 + c4: handles 4 channels x ~13 bins. Warp = 32 consecutive
// c4 -> every corner load is one LDG.128 covering 512B contiguous (coalesced).
// Staging bin-major (pitch 260 floats, 16B aligned): conflict-free STS.128.
// Flush re-orders to [c][bin] with coalesced float4 STG.
// ---------------------------------------------------------------------------
__global__ void __launch_bounds__(256) roi_kernel(const float* __restrict__ boxes,
                                                  float* __restrict__ out)
{
    extern __shared__ float s_out[];                 // 49 * SOPITCH floats
    __shared__ int   s_rs[OH], s_re[OH], s_cs[OW], s_ce[OW];
    __shared__ int   s_csSeg[OW], s_ceSeg[OW];
    __shared__ float s_inv[OH * OW];

    const int n = blockIdx.x;
    const int t = threadIdx.x;

    if (t < OH) {
        const float sc = 0.25f;                      // 200/800, exact in fp32
        int bx1 = (int)floorf(boxes[n * 4 + 0] * sc);
        int by1 = (int)floorf(boxes[n * 4 + 1] * sc);
        int bx2 = (int)floorf(boxes[n * 4 + 2] * sc);
        int by2 = (int)floorf(boxes[n * 4 + 3] * sc);
        int x1 = min(max(bx1, 0), W - 1);
        int y1 = min(max(by1, 0), H - 1);
        int x2 = min(max(bx2 + 1, x1 + 1), W);
        int y2 = min(max(by2 + 1, y1 + 1), H);
        int rh = y2 - y1, rw = x2 - x1;
        int i = t;
        s_rs[i] = y1 + (i * rh) / OH;
        s_re[i] = y1 + ((i + 1) * rh + OH - 1) / OH;
        int csv = x1 + (i * rw) / OW;
        int cev = x1 + ((i + 1) * rw + OW - 1) / OW;
        s_cs[i] = csv;
        s_ce[i] = cev;
        s_csSeg[i] = max(csv - 1, 0) / LSEG;         // cs==0 -> seg0 (prefix 0)
        s_ceSeg[i] = (cev - 1) / LSEG;               // ce >= 1 always
    }
    __syncthreads();
    if (t < OH * OW) {
        int i = t / OW, j = t % OW;
        s_inv[t] = 1.0f / (float)((s_re[i] - s_rs[i]) * (s_ce[j] - s_cs[j]));
    }
    __syncthreads();

    const int c4 = t & (C4 - 1);
    const int bg = t >> 6;                           // 0..3
    const float4* ii4 = (const float4*)g_ii + c4;
    const float4* rp4 = (const float4*)g_rowsum + c4;

    int b0 = bg * 13;
    int b1 = min(OH * OW, b0 + 13);                  // 13,13,13,10
    for (int bin = b0; bin < b1; bin++) {
        int i = bin / OW, j = bin - i * OW;
        int rA = s_rs[i], rB = s_re[i];
        int kA = s_cs[j], kB = s_ce[j];
        int sA = s_csSeg[j], sB = s_ceSeg[j];
        float4 a = ii4[(rB * WP + kB) * C4];
        float4 b = ii4[(rA * WP + kB) * C4];
        float4 e = ii4[(rB * WP + kA) * C4];
        float4 d = ii4[(rA * WP + kA) * C4];
        float4 p = rp4[(sB * HP + rB) * C4];
        float4 q = rp4[(sB * HP + rA) * C4];
        float4 u = rp4[(sA * HP + rB) * C4];
        float4 w = rp4[(sA * HP + rA) * C4];
        float inv = s_inv[bin];
        float4 v;
        v.x = (a.x - b.x - e.x + d.x + p.x - q.x - u.x + w.x) * inv;
        v.y = (a.y - b.y - e.y + d.y + p.y - q.y - u.y + w.y) * inv;
        v.z = (a.z - b.z - e.z + d.z + p.z - q.z - u.z + w.z) * inv;
        v.w = (a.w - b.w - e.w + d.w + p.w - q.w - u.w + w.w) * inv;
        *(float4*)(s_out + bin * SOPITCH + c4 * 4) = v;   // conflict-free STS.128
    }
    __syncthreads();

    // Flush: out[n][c][bin] (c-major). q = c*49 + bin -> smem bin*SOPITCH + c.
    float4* dst = (float4*)(out + (size_t)n * C * (OH * OW));
    const int NQ4 = (C * OH * OW) / 4;               // 3136
    for (int q4 = t; q4 < NQ4; q4 += 256) {
        int q = q4 * 4;
        float4 v;
        {
            int cc = q / 49,       bb = q - cc * 49;       v.x = s_out[bb * SOPITCH + cc];
        }
        {
            int cc = (q + 1) / 49, bb = (q + 1) - cc * 49; v.y = s_out[bb * SOPITCH + cc];
        }
        {
            int cc = (q + 2) / 49, bb = (q + 2) - cc * 49; v.z = s_out[bb * SOPITCH + cc];
        }
        {
            int cc = (q + 3) / 49, bb = (q + 3) - cc * 49; v.w = s_out[bb * SOPITCH + cc];
        }
        dst[q4] = v;
    }
}

// ---------------------------------------------------------------------------
extern "C" void kernel_launch(void* const* d_in, const int* in_sizes, int n_in,
                              void* d_out, int out_size)
{
    const float* fm    = (const float*)d_in[0];
    const float* boxes = (const float*)d_in[1];
    if (n_in >= 2 && in_sizes[0] < in_sizes[1]) {
        fm    = (const float*)d_in[1];
        boxes = (const float*)d_in[0];
    }
    float* out = (float*)d_out;

    // roi_kernel dynamic smem: 49 * 260 * 4 = 50960 B (> 48 KB default)
    const int roi_smem = OH * OW * SOPITCH * (int)sizeof(float);
    cudaFuncSetAttribute(roi_kernel, cudaFuncAttributeMaxDynamicSharedMemorySize,
                         roi_smem);

    // 1) fused transpose + segmented y-scan
    {
        dim3 grid((W + 31) / 32, C / 32, SEG);
        dim3 block(32, 8);
        yscan_kernel<<<grid, block>>>(fm);
    }
    // 2) y-segment exclusive prefix (warp shuffle, one warp per (x,c4))
    {
        int total = W * C4 * 32;                     // 409,600
        colprefix_kernel<<<(total + 255) / 256, 256>>>();
    }
    // 3) segmented x-scan + fused y-fixup (float4)
    xscan_kernel<<<(SEG * H * C4) / 256, 256>>>();
    // 4) x-segment exclusive prefix (warp shuffle) + ii border zeroing
    {
        int total = NPFXW * 32 + WP * C4 + H * C4;   // 437,312
        rowprefix_border_kernel<<<(total + 255) / 256, 256>>>();
    }
    // 5) ROI pooling output (float4 gather, x-fixup fused)
    roi_kernel<<<NBOX, 256, roi_smem>>>(boxes, out);
}

// round 15
// speedup vs baseline: 1.4747x; 1.0629x over previous
#include <cuda_runtime.h>
#include <cuda_bf16.h>

#define C    256
#define C4   64          // C / 4
#define H    200
#define W    200
#define HP   201
#define WP   201
#define NBOX 1024
#define OH   7
#define OW   7
#define SEG  20          // segments for BOTH y-scan and x-scan
#define LSEG 10          // 200 / 20
#define YCH  5           // y-rows per smem chunk in yscan
#define PT   64          // float4 tasks per prefix block
#define RPITCH 132       // roi smem staging pitch (floats per bin row, 16B-aligned)

// Integral image [r][col][c] (channel-innermost); partial-x-scan after xscan_kernel
__device__ float g_ii[HP * WP * C];          // 41.4 MB
// Per-y-segment column totals -> exclusive prefix (y fixup), [seg][x][c]
__device__ float g_colsum[SEG * W * C];      // 4.1 MB
// Per-x-segment row totals -> exclusive prefix (x fixup), [seg][r][c]
__device__ float g_rowsum[SEG * HP * C];     // 4.1 MB

// ---------------------------------------------------------------------------
// Kernel 1: fused transpose + segmented y-scan (champion, unchanged).
// ---------------------------------------------------------------------------
__global__ void __launch_bounds__(256) yscan_kernel(const float* __restrict__ fm) {
    __shared__ float tile[YCH][32][33];   // [y][c_local][x_local]
    const int x0 = blockIdx.x * 32;
    const int c0 = blockIdx.y * 32;
    const int y0 = blockIdx.z * LSEG;
    const int tx = threadIdx.x;           // 0..31
    const int ty = threadIdx.y;           // 0..7
    const int cS = c0 + tx;               // owned channel (store side)
    const bool xinL = (x0 + tx) < W;

    float run[4] = {0.f, 0.f, 0.f, 0.f};

#pragma unroll
    for (int ch = 0; ch < LSEG / YCH; ch++) {
        int yb = y0 + ch * YCH;
#pragma unroll
        for (int yy = 0; yy < YCH; yy++) {
#pragma unroll
            for (int k = 0; k < 4; k++) {
                int cl = ty + 8 * k;
                tile[yy][cl][tx] =
                    xinL ? fm[((c0 + cl) * H + (yb + yy)) * W + (x0 + tx)] : 0.f;
            }
        }
        __syncthreads();
#pragma unroll
        for (int yy = 0; yy < YCH; yy++) {
            int y = yb + yy;
#pragma unroll
            for (int k = 0; k < 4; k++) {
                int xl = ty + 8 * k;
                run[k] += tile[yy][tx][xl];
                int x = x0 + xl;
                if (x < W)
                    g_ii[((y + 1) * WP + (x + 1)) * C + cS] = run[k];
            }
        }
        __syncthreads();
    }
#pragma unroll
    for (int k = 0; k < 4; k++) {
        int x = x0 + ty + 8 * k;
        if (x < W)
            g_colsum[(blockIdx.z * W + x) * C + cS] = run[k];
    }
}

// ---------------------------------------------------------------------------
// Warp-shuffle exclusive scan of a float4 over lanes (lane = segment).
// ---------------------------------------------------------------------------
__device__ __forceinline__ float4 warp_excl_scan4(float4 v, int lane) {
    float4 s = v;
#pragma unroll
    for (int d = 1; d < 32; d <<= 1) {
        float ax = __shfl_up_sync(0xffffffffu, s.x, d);
        float ay = __shfl_up_sync(0xffffffffu, s.y, d);
        float az = __shfl_up_sync(0xffffffffu, s.z, d);
        float aw = __shfl_up_sync(0xffffffffu, s.w, d);
        if (lane >= d) { s.x += ax; s.y += ay; s.z += az; s.w += aw; }
    }
    return make_float4(s.x - v.x, s.y - v.y, s.z - v.z, s.w - v.w);
}

// ---------------------------------------------------------------------------
// Kernel 2: staged colsum prefix (coalesced load -> smem -> shuffle scan ->
// coalesced store) + g_ii border zeroing on tail blocks.
// colsum tasks: W*C4 = 12800 float4 columns, 200 blocks of PT=64.
// ---------------------------------------------------------------------------
#define NCOLBLK (W * C4 / PT)                 // 200
__global__ void __launch_bounds__(256) colprefix_border_kernel() {
    if (blockIdx.x < NCOLBLK) {
        __shared__ float4 sm[SEG][PT + 1];    // 20*65*16 = 20.8 KB
        const int base = blockIdx.x * PT;
        const int t = threadIdx.x;
        float4* p = (float4*)g_colsum;
        for (int idx = t; idx < SEG * PT; idx += 256) {
            int seg = idx / PT, task = idx - seg * PT;
            sm[seg][task] = p[seg * (W * C4) + base + task];   // 1KB contig/seg
        }
        __syncthreads();
        int w = t >> 5, lane = t & 31;
#pragma unroll
        for (int tt = 0; tt < PT / 8; tt++) {
            int task = w * (PT / 8) + tt;
            float4 v = (lane < SEG) ? sm[lane][task]
                                    : make_float4(0.f, 0.f, 0.f, 0.f);
            float4 e = warp_excl_scan4(v, lane);
            if (lane < SEG) sm[lane][task] = e;
        }
        __syncthreads();
        for (int idx = t; idx < SEG * PT; idx += 256) {
            int seg = idx / PT, task = idx - seg * PT;
            p[seg * (W * C4) + base + task] = sm[seg][task];
        }
    } else {
        // border zeroing of g_ii (row r==0, col k==0)
        int t2 = (blockIdx.x - NCOLBLK) * 256 + threadIdx.x;
        const float4 z = {0.f, 0.f, 0.f, 0.f};
        if (t2 < WP * C4) {
            ((float4*)g_ii)[t2] = z;                      // row r==0
        } else if (t2 < WP * C4 + H * C4) {
            int kk = t2 - WP * C4;
            int r  = kk / C4 + 1;
            int c4 = kk & (C4 - 1);
            ((float4*)g_ii)[(r * WP) * C4 + c4] = z;      // col k==0
        }
    }
}
#define NBORDBLK ((WP * C4 + H * C4 + 255) / 256)         // 101

// ---------------------------------------------------------------------------
// Kernel 3: segmented x-scan + fused y-fixup, float4 (champion, unchanged).
// ---------------------------------------------------------------------------
__global__ void __launch_bounds__(256) xscan_kernel() {
    int t  = blockIdx.x * blockDim.x + threadIdx.x;
    int c4 = t & (C4 - 1);
    int y  = (t >> 6) % H;
    int sx = t / (C4 * H);
    int sy = y / LSEG;
    int r  = y + 1;
    float4* ii = (float4*)g_ii;
    const float4* cp = (const float4*)g_colsum + (sy * W) * C4 + c4;
    float4 run = {0.f, 0.f, 0.f, 0.f};
    int x0 = sx * LSEG;
#pragma unroll 5
    for (int xx = 0; xx < LSEG; xx++) {
        int x   = x0 + xx;
        int off = (r * WP + (x + 1)) * C4 + c4;
        float4 v = ii[off];
        float4 a = cp[x * C4];
        run.x += v.x + a.x;
        run.y += v.y + a.y;
        run.z += v.z + a.z;
        run.w += v.w + a.w;
        ii[off] = run;
    }
    ((float4*)g_rowsum)[(sx * HP + r) * C4 + c4] = run;
}

// ---------------------------------------------------------------------------
// Kernel 4: staged rowsum prefix (same 3-phase pattern). r==0 forced to zero.
// Tasks: HP*C4 = 12864 float4 columns, 201 blocks of PT=64.
// ---------------------------------------------------------------------------
__global__ void __launch_bounds__(256) rowprefix_kernel() {
    __shared__ float4 sm[SEG][PT + 1];
    const int base = blockIdx.x * PT;
    const int t = threadIdx.x;
    float4* p = (float4*)g_rowsum;
    for (int idx = t; idx < SEG * PT; idx += 256) {
        int seg = idx / PT, task = idx - seg * PT;
        int g = base + task;
        sm[seg][task] = (g >= C4)                       // r>0 only; r==0 -> 0
            ? p[seg * (HP * C4) + g]
            : make_float4(0.f, 0.f, 0.f, 0.f);
    }
    __syncthreads();
    int w = t >> 5, lane = t & 31;
#pragma unroll
    for (int tt = 0; tt < PT / 8; tt++) {
        int task = w * (PT / 8) + tt;
        float4 v = (lane < SEG) ? sm[lane][task]
                                : make_float4(0.f, 0.f, 0.f, 0.f);
        float4 e = warp_excl_scan4(v, lane);
        if (lane < SEG) sm[lane][task] = e;
    }
    __syncthreads();
    for (int idx = t; idx < SEG * PT; idx += 256) {
        int seg = idx / PT, task = idx - seg * PT;
        p[seg * (HP * C4) + base + task] = sm[seg][task];
    }
}

// ---------------------------------------------------------------------------
// Kernel 5: ROI pooling output, float4 over channels, 2 blocks per box
// (channel halves) -> 25.9 KB staging -> 8 blocks/SM.
// Warp = 32 consecutive c4 -> 512B coalesced LDG.128 per corner.
// ---------------------------------------------------------------------------
__global__ void __launch_bounds__(256) roi_kernel(const float* __restrict__ boxes,
                                                  float* __restrict__ out)
{
    extern __shared__ float s_out[];                 // 49 * RPITCH floats
    __shared__ int   s_rs[OH], s_re[OH], s_cs[OW], s_ce[OW];
    __shared__ int   s_csSeg[OW], s_ceSeg[OW];
    __shared__ float s_inv[OH * OW];

    const int n    = blockIdx.x;
    const int half = blockIdx.y;                     // 0: c<128, 1: c>=128
    const int t    = threadIdx.x;

    if (t < OH) {
        const float sc = 0.25f;                      // 200/800, exact in fp32
        int bx1 = (int)floorf(boxes[n * 4 + 0] * sc);
        int by1 = (int)floorf(boxes[n * 4 + 1] * sc);
        int bx2 = (int)floorf(boxes[n * 4 + 2] * sc);
        int by2 = (int)floorf(boxes[n * 4 + 3] * sc);
        int x1 = min(max(bx1, 0), W - 1);
        int y1 = min(max(by1, 0), H - 1);
        int x2 = min(max(bx2 + 1, x1 + 1), W);
        int y2 = min(max(by2 + 1, y1 + 1), H);
        int rh = y2 - y1, rw = x2 - x1;
        int i = t;
        s_rs[i] = y1 + (i * rh) / OH;
        s_re[i] = y1 + ((i + 1) * rh + OH - 1) / OH;
        int csv = x1 + (i * rw) / OW;
        int cev = x1 + ((i + 1) * rw + OW - 1) / OW;
        s_cs[i] = csv;
        s_ce[i] = cev;
        s_csSeg[i] = max(csv - 1, 0) / LSEG;         // cs==0 -> seg0 (prefix 0)
        s_ceSeg[i] = (cev - 1) / LSEG;               // ce >= 1 always
    }
    __syncthreads();
    if (t < OH * OW) {
        int i = t / OW, j = t % OW;
        s_inv[t] = 1.0f / (float)((s_re[i] - s_rs[i]) * (s_ce[j] - s_cs[j]));
    }
    __syncthreads();

    const int c4l = t & 31;                          // local float4 channel
    const int bg  = t >> 5;                          // 0..7 bin groups
    const int co  = half * 32 + c4l;                 // global float4 channel
    const float4* ii4 = (const float4*)g_ii + co;
    const float4* rp4 = (const float4*)g_rowsum + co;

    int b0 = (bg * 49) >> 3;
    int b1 = ((bg + 1) * 49) >> 3;                   // balanced 6/7 bins
    for (int bin = b0; bin < b1; bin++) {
        int i = bin / OW, j = bin - i * OW;
        int rA = s_rs[i], rB = s_re[i];
        int kA = s_cs[j], kB = s_ce[j];
        int sA = s_csSeg[j], sB = s_ceSeg[j];
        float4 a = ii4[(rB * WP + kB) * C4];
        float4 b = ii4[(rA * WP + kB) * C4];
        float4 e = ii4[(rB * WP + kA) * C4];
        float4 d = ii4[(rA * WP + kA) * C4];
        float4 p = rp4[(sB * HP + rB) * C4];
        float4 q = rp4[(sB * HP + rA) * C4];
        float4 u = rp4[(sA * HP + rB) * C4];
        float4 w = rp4[(sA * HP + rA) * C4];
        float inv = s_inv[bin];
        float4 v;
        v.x = (a.x - b.x - e.x + d.x + p.x - q.x - u.x + w.x) * inv;
        v.y = (a.y - b.y - e.y + d.y + p.y - q.y - u.y + w.y) * inv;
        v.z = (a.z - b.z - e.z + d.z + p.z - q.z - u.z + w.z) * inv;
        v.w = (a.w - b.w - e.w + d.w + p.w - q.w - u.w + w.w) * inv;
        *(float4*)(s_out + bin * RPITCH + c4l * 4) = v;   // conflict-free STS.128
    }
    __syncthreads();

    // Flush this half: 128 channels * 49 bins = 6272 floats = 1568 float4.
    float4* dst = (float4*)(out + ((size_t)n * C + half * 128) * (OH * OW));
    const int NQ4 = (128 * OH * OW) / 4;             // 1568
    for (int q4 = t; q4 < NQ4; q4 += 256) {
        int q = q4 * 4;
        float4 v;
        { int cc = q / 49,       bb = q - cc * 49;       v.x = s_out[bb * RPITCH + cc]; }
        { int cc = (q + 1) / 49, bb = (q + 1) - cc * 49; v.y = s_out[bb * RPITCH + cc]; }
        { int cc = (q + 2) / 49, bb = (q + 2) - cc * 49; v.z = s_out[bb * RPITCH + cc]; }
        { int cc = (q + 3) / 49, bb = (q + 3) - cc * 49; v.w = s_out[bb * RPITCH + cc]; }
        dst[q4] = v;
    }
}

// ---------------------------------------------------------------------------
extern "C" void kernel_launch(void* const* d_in, const int* in_sizes, int n_in,
                              void* d_out, int out_size)
{
    const float* fm    = (const float*)d_in[0];
    const float* boxes = (const float*)d_in[1];
    if (n_in >= 2 && in_sizes[0] < in_sizes[1]) {
        fm    = (const float*)d_in[1];
        boxes = (const float*)d_in[0];
    }
    float* out = (float*)d_out;

    // roi_kernel dynamic smem: 49 * 132 * 4 = 25872 B
    const int roi_smem = OH * OW * RPITCH * (int)sizeof(float);
    cudaFuncSetAttribute(roi_kernel, cudaFuncAttributeMaxDynamicSharedMemorySize,
                         roi_smem);

    // 1) fused transpose + segmented y-scan
    {
        dim3 grid((W + 31) / 32, C / 32, SEG);
        dim3 block(32, 8);
        yscan_kernel<<<grid, block>>>(fm);
    }
    // 2) staged colsum prefix + ii border zeroing
    colprefix_border_kernel<<<NCOLBLK + NBORDBLK, 256>>>();
    // 3) segmented x-scan + fused y-fixup (float4)
    xscan_kernel<<<(SEG * H * C4) / 256, 256>>>();
    // 4) staged rowsum prefix
    rowprefix_kernel<<<(HP * C4) / PT, 256>>>();
    // 5) ROI pooling output (float4 gather, 2 blocks/box)
    {
        dim3 grid(NBOX, 2);
        roi_kernel<<<grid, 256, roi_smem>>>(boxes, out);
    }
}